// round 9
// baseline (speedup 1.0000x reference)
#include <cuda_runtime.h>
#include <cstdint>

// DeepMapping2D occupancy_generation, GB300 sm_103a.  Round 9.
//
//   output[b] = K_b ones then zeros, K_b = #bins with count >= 53.
//   Min-shift is a bin bijection -> K_b shift-invariant -> no min pass.
//
// Validated model (R4-R8): hist is pinned at the LTS sector-RMW cap
// (~1.07GB ~= 94us); count (read-only) and zero (store-only) are at their
// floors (~9us, ~11.7us). Single-stream total converged at 117.2us.
//
// R9: hide the aux under the hist. 4 groups x 16 batches, two streams
// joined by events (capture-fork). Hist groups chain head-to-tail (the
// scatter keeps the whole chip); each group's count+zero overlaps the NEXT
// group's hist, which runs at 76% L2 and can absorb it. Only the last
// group's aux + OUT are exposed. Kernel bodies = proven R8 shapes.

#define NBATCH  64
#define NPTS    262144
#define TOPK    5120
#define GZ_LOG2 10
#define BINS_PER_BATCH   (1024u * 1024u)          // 1M u8 bins / batch
#define HWORDS_PER_BATCH (BINS_PER_BATCH / 4)     // 256K u32 / batch
#define GB      16                                 // batches per group

__device__ unsigned int g_hist[(size_t)NBATCH * HWORDS_PER_BATCH];  // 64 MB, load-zeroed
__device__ unsigned int g_count[NBATCH];                            // load-zeroed

// ---------------------------------------------------------------------------
// Histogram scatter for one 16-batch group. grid (64, GB) x 256.
// RED-only byte adds (R4/R7 proven shape).
// ---------------------------------------------------------------------------
__global__ void dm2d_hist_kernel(const float4* __restrict__ pcd, int b0) {
    const int b = b0 + blockIdx.y;
    unsigned int* __restrict__ hist = g_hist + (size_t)b * HWORDS_PER_BATCH;
    const float4* __restrict__ base = pcd + (size_t)b * (NPTS / 2);

    const int tid    = blockIdx.x * blockDim.x + threadIdx.x;
    const int stride = gridDim.x * blockDim.x;

    #pragma unroll 4
    for (int i = tid; i < NPTS / 2; i += stride) {
        float4 p = __ldcs(&base[i]);   // two points: (x0,z0,x1,z1); evict-first

        // jnp.round = round-half-to-even == rintf under default RN mode.
        unsigned x0 = (unsigned)(int)rintf(1000.0f * p.x);
        unsigned z0 = (unsigned)(int)rintf(1000.0f * p.y);
        unsigned x1 = (unsigned)(int)rintf(1000.0f * p.z);
        unsigned z1 = (unsigned)(int)rintf(1000.0f * p.w);

        unsigned i0 = (x0 << GZ_LOG2) | z0;
        unsigned i1 = (x1 << GZ_LOG2) | z1;

        atomicAdd(&hist[i0 >> 2], 1u << ((i0 & 3u) << 3));  // REDG
        atomicAdd(&hist[i1 >> 2], 1u << ((i1 & 3u) << 3));
    }
}

// ---------------------------------------------------------------------------
// Count bins >= 53 for one group. READ-ONLY. grid (32, GB) x 256;
// 8 uint4 = 128 bins / thread.
// ---------------------------------------------------------------------------
__global__ void dm2d_count_kernel(int b0) {
    const int b = b0 + blockIdx.y;
    const uint4* __restrict__ hist4 =
        reinterpret_cast<const uint4*>(g_hist + (size_t)b * HWORDS_PER_BATCH);

    const int tid = blockIdx.x * 256 + threadIdx.x;   // 0..8191

    unsigned int cnt = 0;
    #pragma unroll
    for (int u = 0; u < 8; u++) {
        uint4 w = hist4[tid + u * 8192];
        cnt += __popc(__vcmpgeu4(w.x, 0x35353535u) & 0x01010101u);
        cnt += __popc(__vcmpgeu4(w.y, 0x35353535u) & 0x01010101u);
        cnt += __popc(__vcmpgeu4(w.z, 0x35353535u) & 0x01010101u);
        cnt += __popc(__vcmpgeu4(w.w, 0x35353535u) & 0x01010101u);
    }

    #pragma unroll
    for (int off = 16; off > 0; off >>= 1)
        cnt += __shfl_down_sync(0xFFFFFFFFu, cnt, off);
    if ((threadIdx.x & 31) == 0 && cnt)
        atomicAdd(&g_count[b], cnt);
}

// ---------------------------------------------------------------------------
// Pure-store re-zero of one group's histogram (for the next replay).
// grid (64, GB) x 256; 4 uint4 / thread.
// ---------------------------------------------------------------------------
__global__ void dm2d_zero_kernel(int b0) {
    const int b = b0 + blockIdx.y;
    uint4* __restrict__ hist4 =
        reinterpret_cast<uint4*>(g_hist + (size_t)b * HWORDS_PER_BATCH);

    const int tid = blockIdx.x * 256 + threadIdx.x;   // 0..16383
    const uint4 zero4 = make_uint4(0u, 0u, 0u, 0u);
    #pragma unroll
    for (int u = 0; u < 4; u++)
        hist4[tid + u * 16384] = zero4;
}

// ---------------------------------------------------------------------------
// Output expansion + counter reset. grid 64 x 256.
// ---------------------------------------------------------------------------
__global__ void dm2d_out_kernel(float* __restrict__ out) {
    const int b = blockIdx.x;
    const int K = (int)g_count[b];
    float* ob = out + (size_t)b * TOPK;
    #pragma unroll
    for (int u = 0; u < TOPK / 256; u++) {
        int i = u * 256 + threadIdx.x;
        ob[i] = (i < K) ? 1.0f : 0.0f;
    }
    __syncthreads();
    if (threadIdx.x == 0) g_count[b] = 0u;            // reset for next replay
}

extern "C" void kernel_launch(void* const* d_in, const int* in_sizes, int n_in,
                              void* d_out, int out_size) {
    (void)in_sizes; (void)n_in; (void)out_size;
    const float4* pcd = reinterpret_cast<const float4*>(d_in[0]);
    float* out = reinterpret_cast<float*>(d_out);

    const dim3 hg(64, GB), cg(32, GB), zg(64, GB);

    cudaStream_t s1 = nullptr;
    cudaEvent_t eH0 = nullptr, eH1 = nullptr, eH2 = nullptr, eJoin = nullptr;
    bool forked =
        cudaStreamCreateWithFlags(&s1, cudaStreamNonBlocking) == cudaSuccess &&
        cudaEventCreateWithFlags(&eH0, cudaEventDisableTiming) == cudaSuccess &&
        cudaEventCreateWithFlags(&eH1, cudaEventDisableTiming) == cudaSuccess &&
        cudaEventCreateWithFlags(&eH2, cudaEventDisableTiming) == cudaSuccess &&
        cudaEventCreateWithFlags(&eJoin, cudaEventDisableTiming) == cudaSuccess;

    if (forked) {
        // group 0 on s0 (default stream)
        dm2d_hist_kernel<<<hg, 256>>>(pcd, 0 * GB);
        cudaEventRecord(eH0, 0);
        // group 1 hist on s1, chained after H0
        cudaStreamWaitEvent(s1, eH0, 0);
        dm2d_hist_kernel<<<hg, 256, 0, s1>>>(pcd, 1 * GB);
        cudaEventRecord(eH1, s1);
        // aux g0 on s0 (overlaps H1)
        dm2d_count_kernel<<<cg, 256>>>(0 * GB);
        dm2d_zero_kernel<<<zg, 256>>>(0 * GB);
        // group 2 hist on s0, chained after H1
        cudaStreamWaitEvent(0, eH1, 0);
        dm2d_hist_kernel<<<hg, 256>>>(pcd, 2 * GB);
        cudaEventRecord(eH2, 0);
        // aux g1 on s1 (overlaps H2)
        dm2d_count_kernel<<<cg, 256, 0, s1>>>(1 * GB);
        dm2d_zero_kernel<<<zg, 256, 0, s1>>>(1 * GB);
        // group 3 hist on s1, chained after H2
        cudaStreamWaitEvent(s1, eH2, 0);
        dm2d_hist_kernel<<<hg, 256, 0, s1>>>(pcd, 3 * GB);
        // aux g3 on s1 (tail-exposed)
        dm2d_count_kernel<<<cg, 256, 0, s1>>>(3 * GB);
        dm2d_zero_kernel<<<zg, 256, 0, s1>>>(3 * GB);
        cudaEventRecord(eJoin, s1);
        // aux g2 on s0 (overlaps H3 on s1)
        dm2d_count_kernel<<<cg, 256>>>(2 * GB);
        dm2d_zero_kernel<<<zg, 256>>>(2 * GB);
        // join s1 back into s0, then write output
        cudaStreamWaitEvent(0, eJoin, 0);
        dm2d_out_kernel<<<NBATCH, 256>>>(out);
    } else {
        // sequential fallback (== R8 structure)
        for (int g = 0; g < 4; g++) dm2d_hist_kernel<<<hg, 256>>>(pcd, g * GB);
        for (int g = 0; g < 4; g++) dm2d_count_kernel<<<cg, 256>>>(g * GB);
        for (int g = 0; g < 4; g++) dm2d_zero_kernel<<<zg, 256>>>(g * GB);
        dm2d_out_kernel<<<NBATCH, 256>>>(out);
    }
}

// round 10
// speedup vs baseline: 1.1429x; 1.1429x over previous
#include <cuda_runtime.h>
#include <cstdint>

// DeepMapping2D occupancy_generation, GB300 sm_103a.  Round 10.
//
//   output[b] = K_b ones then zeros, K_b = #bins with count >= 53.
//   Min-shift is a bin bijection -> K_b shift-invariant -> no min pass.
//
// Validated model (R4-R9):
//   * hist pinned at the LTS atomic-ALU floor (~2cyc/sector-RMW x 16.7M /
//     184 LTS ~= 94us). REDG only; no returns (R6 +44us); no extra MLP
//     (R5); no stream-forking (R9 +16us). Hist loop is byte-identical to
//     the R7/R8 best.
//   * count (read-only, ~9us) and zero (store-only) are separate kernels;
//     fusing load+store on the same lines is poison (R3/R4).
// R10: kill the zero_out tail -- output expansion is distributed across the
// zero grid as float4 writes (no designated CTA, no __syncthreads), and the
// g_count reset moves to the top of the NEXT replay's hist kernel (kernel
// boundaries provide all ordering; state invariant identical every call).

#define NBATCH  64
#define NPTS    262144
#define TOPK    5120
#define GZ_LOG2 10
#define BINS_PER_BATCH   (1024u * 1024u)          // 1M u8 bins / batch
#define HWORDS_PER_BATCH (BINS_PER_BATCH / 4)     // 256K u32 / batch
#define OUT_F4_PER_BATCH (TOPK / 4)               // 1280 float4 per batch

__device__ unsigned int g_hist[(size_t)NBATCH * HWORDS_PER_BATCH];  // 64 MB, load-zeroed
__device__ unsigned int g_count[NBATCH];                            // load-zeroed

// ---------------------------------------------------------------------------
// Kernel 1: histogram scatter, RED-only byte adds + per-batch counter reset.
// grid (64, 64) x 256 thr; grid-stride, unroll 4. Measured 93.9-95.4us.
// The reset is ordered before this replay's count kernel by the kernel
// boundary; nothing else touches g_count during hist.
// ---------------------------------------------------------------------------
__global__ void dm2d_hist_kernel(const float4* __restrict__ pcd) {
    const int b = blockIdx.y;
    if (blockIdx.x == 0 && threadIdx.x == 0)
        g_count[b] = 0u;                           // reset (prev replay's value)

    unsigned int* __restrict__ hist = g_hist + (size_t)b * HWORDS_PER_BATCH;
    const float4* __restrict__ base = pcd + (size_t)b * (NPTS / 2);

    const int tid    = blockIdx.x * blockDim.x + threadIdx.x;
    const int stride = gridDim.x * blockDim.x;

    #pragma unroll 4
    for (int i = tid; i < NPTS / 2; i += stride) {
        float4 p = __ldcs(&base[i]);   // two points: (x0,z0,x1,z1); evict-first

        // jnp.round = round-half-to-even == rintf under default RN mode.
        unsigned x0 = (unsigned)(int)rintf(1000.0f * p.x);
        unsigned z0 = (unsigned)(int)rintf(1000.0f * p.y);
        unsigned x1 = (unsigned)(int)rintf(1000.0f * p.z);
        unsigned z1 = (unsigned)(int)rintf(1000.0f * p.w);

        unsigned i0 = (x0 << GZ_LOG2) | z0;
        unsigned i1 = (x1 << GZ_LOG2) | z1;

        // fire-and-forget byte increments (return unused -> REDG)
        atomicAdd(&hist[i0 >> 2], 1u << ((i0 & 3u) << 3));
        atomicAdd(&hist[i1 >> 2], 1u << ((i1 & 3u) << 3));
    }
}

// ---------------------------------------------------------------------------
// Kernel 2: count bins >= 53 per batch. READ-ONLY over the L2-resident hist.
// grid (64, 64) x 256 thr; 4 uint4 = 64 bins per thread. Measured ~9us.
// ---------------------------------------------------------------------------
__global__ void dm2d_count_kernel() {
    const int b = blockIdx.y;
    const uint4* __restrict__ hist4 =
        reinterpret_cast<const uint4*>(g_hist + (size_t)b * HWORDS_PER_BATCH);

    const int tid = blockIdx.x * 256 + threadIdx.x;   // 0..16383

    unsigned int cnt = 0;
    #pragma unroll
    for (int u = 0; u < 4; u++) {
        uint4 w = hist4[tid + u * 16384];
        cnt += __popc(__vcmpgeu4(w.x, 0x35353535u) & 0x01010101u);
        cnt += __popc(__vcmpgeu4(w.y, 0x35353535u) & 0x01010101u);
        cnt += __popc(__vcmpgeu4(w.z, 0x35353535u) & 0x01010101u);
        cnt += __popc(__vcmpgeu4(w.w, 0x35353535u) & 0x01010101u);
    }

    #pragma unroll
    for (int off = 16; off > 0; off >>= 1)
        cnt += __shfl_down_sync(0xFFFFFFFFu, cnt, off);
    if ((threadIdx.x & 31) == 0 && cnt)
        atomicAdd(&g_count[b], cnt);
}

// ---------------------------------------------------------------------------
// Kernel 3: pure-store re-zero of the histogram + DISTRIBUTED output write.
// grid (64, 64) x 256 thr. Each thread: 4 uint4 zero stores; threads with
// tid < 1280 in each batch slice additionally write one float4 of output.
// No tail CTA, no __syncthreads, no reset (hist does it next replay).
// ---------------------------------------------------------------------------
__global__ void dm2d_zero_out_kernel(float* __restrict__ out) {
    const int b = blockIdx.y;
    uint4* __restrict__ hist4 =
        reinterpret_cast<uint4*>(g_hist + (size_t)b * HWORDS_PER_BATCH);

    const int tid = blockIdx.x * 256 + threadIdx.x;   // 0..16383
    const uint4 zero4 = make_uint4(0u, 0u, 0u, 0u);
    #pragma unroll
    for (int u = 0; u < 4; u++)
        hist4[tid + u * 16384] = zero4;               // pure stores, stay L2-dirty

    if (tid < OUT_F4_PER_BATCH) {
        const int K = (int)g_count[b];                // set by K2 (launch-ordered)
        const int i = tid * 4;
        float4 v;
        v.x = (i + 0 < K) ? 1.0f : 0.0f;
        v.y = (i + 1 < K) ? 1.0f : 0.0f;
        v.z = (i + 2 < K) ? 1.0f : 0.0f;
        v.w = (i + 3 < K) ? 1.0f : 0.0f;
        reinterpret_cast<float4*>(out + (size_t)b * TOPK)[tid] = v;
    }
}

extern "C" void kernel_launch(void* const* d_in, const int* in_sizes, int n_in,
                              void* d_out, int out_size) {
    (void)in_sizes; (void)n_in; (void)out_size;
    const float4* pcd = reinterpret_cast<const float4*>(d_in[0]);
    float* out = reinterpret_cast<float*>(d_out);

    dim3 grid(64, NBATCH);
    dm2d_hist_kernel<<<grid, 256>>>(pcd);
    dm2d_count_kernel<<<grid, 256>>>();
    dm2d_zero_out_kernel<<<grid, 256>>>(out);
}